// round 1
// baseline (speedup 1.0000x reference)
#include <cuda_runtime.h>
#include <cuda_bf16.h>
#include <cstdint>

// BCE-with-logits mean reduction over 8192x8192.
// loss = mean over elems of softplus( target!=0 ? -x : x )
// Two-pass deterministic reduction (no float atomics).

#define NBLOCKS   1184   // 148 SMs * 8
#define NTHREADS  256

__device__ float g_partials[NBLOCKS];

__global__ __launch_bounds__(NTHREADS) void bce_partial_kernel(
    const float* __restrict__ x, const int* __restrict__ t, long long n4)
{
    const float4* __restrict__ x4 = (const float4*)x;
    const int4*   __restrict__ t4 = (const int4*)t;

    float acc = 0.0f;
    long long stride = (long long)gridDim.x * blockDim.x;
    for (long long i = (long long)blockIdx.x * blockDim.x + threadIdx.x;
         i < n4; i += stride) {
        float4 xv = x4[i];
        int4   tv = t4[i];

        // y = (t != 0) ? -x : x ; loss = softplus(y) = max(y,0) + log(1+exp(-|y|))
        float y0 = tv.x ? -xv.x : xv.x;
        float y1 = tv.y ? -xv.y : xv.y;
        float y2 = tv.z ? -xv.z : xv.z;
        float y3 = tv.w ? -xv.w : xv.w;

        float s0 = fmaxf(y0, 0.0f) + __logf(1.0f + __expf(-fabsf(y0)));
        float s1 = fmaxf(y1, 0.0f) + __logf(1.0f + __expf(-fabsf(y1)));
        float s2 = fmaxf(y2, 0.0f) + __logf(1.0f + __expf(-fabsf(y2)));
        float s3 = fmaxf(y3, 0.0f) + __logf(1.0f + __expf(-fabsf(y3)));

        acc += (s0 + s1) + (s2 + s3);
    }

    // Block reduction (warp shuffle + smem)
    __shared__ float warp_sums[NTHREADS / 32];
    #pragma unroll
    for (int off = 16; off > 0; off >>= 1)
        acc += __shfl_down_sync(0xFFFFFFFFu, acc, off);
    int lane = threadIdx.x & 31;
    int wid  = threadIdx.x >> 5;
    if (lane == 0) warp_sums[wid] = acc;
    __syncthreads();
    if (wid == 0) {
        float v = (lane < NTHREADS / 32) ? warp_sums[lane] : 0.0f;
        #pragma unroll
        for (int off = 16; off > 0; off >>= 1)
            v += __shfl_down_sync(0xFFFFFFFFu, v, off);
        if (lane == 0) g_partials[blockIdx.x] = v;
    }
}

__global__ __launch_bounds__(NTHREADS) void bce_finish_kernel(
    float* __restrict__ out, float inv_n)
{
    float acc = 0.0f;
    for (int i = threadIdx.x; i < NBLOCKS; i += NTHREADS)
        acc += g_partials[i];

    __shared__ float warp_sums[NTHREADS / 32];
    #pragma unroll
    for (int off = 16; off > 0; off >>= 1)
        acc += __shfl_down_sync(0xFFFFFFFFu, acc, off);
    int lane = threadIdx.x & 31;
    int wid  = threadIdx.x >> 5;
    if (lane == 0) warp_sums[wid] = acc;
    __syncthreads();
    if (wid == 0) {
        float v = (lane < NTHREADS / 32) ? warp_sums[lane] : 0.0f;
        #pragma unroll
        for (int off = 16; off > 0; off >>= 1)
            v += __shfl_down_sync(0xFFFFFFFFu, v, off);
        if (lane == 0) out[0] = v * inv_n;
    }
}

extern "C" void kernel_launch(void* const* d_in, const int* in_sizes, int n_in,
                              void* d_out, int out_size)
{
    const float* x = (const float*)d_in[0];
    const int*   t = (const int*)d_in[1];
    float* out = (float*)d_out;

    long long n  = (long long)in_sizes[0];   // 64M, divisible by 4
    long long n4 = n >> 2;

    bce_partial_kernel<<<NBLOCKS, NTHREADS>>>(x, t, n4);
    bce_finish_kernel<<<1, NTHREADS>>>(out, 1.0f / (float)n);
}